// round 1
// baseline (speedup 1.0000x reference)
#include <cuda_runtime.h>

// LIF forward scan.
// x: [B=32, T=64, N=16384] f32
// thresh, tau_x: [N] f32
// out: spikes [B,T,N] f32 followed by mems [B,T,N] f32 (post-reset membrane).
//
// One thread owns 4 adjacent neurons (float4) for one batch row and walks
// T=64 steps. Loads of x[t] are independent of the membrane carry, so the
// unrolled loop software-pipelines them (MLP>=4), keeping HBM saturated.

static constexpr int B = 32;
static constexpr int T = 64;
static constexpr int N = 16384;
static constexpr int N4 = N / 4;          // 4096 float4 lanes per row

__global__ __launch_bounds__(256) void lif_kernel(
    const float4* __restrict__ x,         // [B, T, N4]
    const float4* __restrict__ thresh4,   // [N4]
    const float4* __restrict__ taux4,     // [N4]
    float4* __restrict__ spikes,          // [B, T, N4]
    float4* __restrict__ mems)            // [B, T, N4]
{
    const int idx = blockIdx.x * blockDim.x + threadIdx.x;  // [0, B*N4)
    const int n4 = idx & (N4 - 1);
    const int b  = idx >> 12;             // idx / N4

    const float4 th = thresh4[n4];
    const float4 tx = taux4[n4];

    // sigmoid(tau_x), constant over timesteps
    float4 sig;
    sig.x = 1.0f / (1.0f + __expf(-tx.x));
    sig.y = 1.0f / (1.0f + __expf(-tx.y));
    sig.z = 1.0f / (1.0f + __expf(-tx.z));
    sig.w = 1.0f / (1.0f + __expf(-tx.w));

    float4 mem = make_float4(0.f, 0.f, 0.f, 0.f);

    const size_t base = (size_t)b * T * N4 + n4;
    const float4* xp = x + base;
    float4* sp = spikes + base;
    float4* mp = mems + base;

    #pragma unroll 8
    for (int t = 0; t < T; ++t) {
        const float4 xv = xp[(size_t)t * N4];

        // leaky integration: mem += sig * (x - mem)
        mem.x = fmaf(sig.x, xv.x - mem.x, mem.x);
        mem.y = fmaf(sig.y, xv.y - mem.y, mem.y);
        mem.z = fmaf(sig.z, xv.z - mem.z, mem.z);
        mem.w = fmaf(sig.w, xv.w - mem.w, mem.w);

        // Heaviside fire (>= 0) and hard reset
        float4 s;
        s.x = (mem.x >= th.x) ? 1.0f : 0.0f;
        s.y = (mem.y >= th.y) ? 1.0f : 0.0f;
        s.z = (mem.z >= th.z) ? 1.0f : 0.0f;
        s.w = (mem.w >= th.w) ? 1.0f : 0.0f;

        mem.x = (s.x != 0.0f) ? 0.0f : mem.x;
        mem.y = (s.y != 0.0f) ? 0.0f : mem.y;
        mem.z = (s.z != 0.0f) ? 0.0f : mem.z;
        mem.w = (s.w != 0.0f) ? 0.0f : mem.w;

        sp[(size_t)t * N4] = s;
        mp[(size_t)t * N4] = mem;  // post-reset membrane, matching reference
    }
}

extern "C" void kernel_launch(void* const* d_in, const int* in_sizes, int n_in,
                              void* d_out, int out_size)
{
    const float4* x    = (const float4*)d_in[0];
    const float4* th   = (const float4*)d_in[1];
    const float4* taux = (const float4*)d_in[2];

    float4* spikes = (float4*)d_out;
    float4* mems   = (float4*)((float*)d_out + (size_t)B * T * N);

    const int total = B * N4;             // 131072 threads
    const int tpb = 256;
    lif_kernel<<<total / tpb, tpb>>>(x, th, taux, spikes, mems);
}

// round 2
// speedup vs baseline: 1.0314x; 1.0314x over previous
#include <cuda_runtime.h>

// LIF forward scan — round 2.
// x: [B=32, T=64, N=16384] f32; thresh, tau_x: [N] f32
// out: spikes [B,T,N] f32 then mems [B,T,N] f32 (post-reset).
//
// float2 lanes (2 neurons/thread) -> 262144 threads -> ~86% occupancy,
// doubling the independent load streams per SM vs the float4 version
// (which was stuck at 40% occ / 69.8% DRAM). Streaming cache hints since
// nothing is reused.

static constexpr int B = 32;
static constexpr int T = 64;
static constexpr int N = 16384;
static constexpr int N2 = N / 2;          // 8192 float2 lanes per row

__global__ __launch_bounds__(256) void lif_kernel(
    const float2* __restrict__ x,         // [B, T, N2]
    const float2* __restrict__ thresh2,   // [N2]
    const float2* __restrict__ taux2,     // [N2]
    float2* __restrict__ spikes,          // [B, T, N2]
    float2* __restrict__ mems)            // [B, T, N2]
{
    const int idx = blockIdx.x * blockDim.x + threadIdx.x;  // [0, B*N2)
    const int n2 = idx & (N2 - 1);
    const int b  = idx >> 13;             // idx / N2

    const float2 th = thresh2[n2];
    const float2 tx = taux2[n2];

    float2 sig;
    sig.x = 1.0f / (1.0f + __expf(-tx.x));
    sig.y = 1.0f / (1.0f + __expf(-tx.y));

    float2 mem = make_float2(0.f, 0.f);

    const size_t base = (size_t)b * T * N2 + n2;
    const float2* xp = x + base;
    float2* sp = spikes + base;
    float2* mp = mems + base;

    #pragma unroll 8
    for (int t = 0; t < T; ++t) {
        const float2 xv = __ldcs(&xp[(size_t)t * N2]);

        // leaky integration: mem += sig * (x - mem)
        float mx = fmaf(sig.x, xv.x - mem.x, mem.x);
        float my = fmaf(sig.y, xv.y - mem.y, mem.y);

        // Heaviside fire (>= threshold) and hard reset
        float2 s;
        s.x = (mx >= th.x) ? 1.0f : 0.0f;
        s.y = (my >= th.y) ? 1.0f : 0.0f;

        mem.x = (s.x != 0.0f) ? 0.0f : mx;
        mem.y = (s.y != 0.0f) ? 0.0f : my;

        __stcs(&sp[(size_t)t * N2], s);
        __stcs(&mp[(size_t)t * N2], mem);
    }
}

extern "C" void kernel_launch(void* const* d_in, const int* in_sizes, int n_in,
                              void* d_out, int out_size)
{
    const float2* x    = (const float2*)d_in[0];
    const float2* th   = (const float2*)d_in[1];
    const float2* taux = (const float2*)d_in[2];

    float2* spikes = (float2*)d_out;
    float2* mems   = (float2*)((float*)d_out + (size_t)B * T * N);

    const int total = B * N2;             // 262144 threads
    const int tpb = 256;
    lif_kernel<<<total / tpb, tpb>>>(x, th, taux, spikes, mems);
}

// round 3
// speedup vs baseline: 1.0356x; 1.0040x over previous
#include <cuda_runtime.h>

// LIF forward scan — round 3.
// float4 lanes (4 neurons/thread), explicit 4-deep load prefetch pipeline so
// every thread always has 4 independent 16B loads in flight (R1 evidence:
// regs=32 meant ptxas wasn't batching loads; MLP~2 capped DRAM at 70%).

static constexpr int B = 32;
static constexpr int T = 64;
static constexpr int N = 16384;
static constexpr int N4 = N / 4;          // 4096 float4 lanes per row

__global__ __launch_bounds__(128) void lif_kernel(
    const float4* __restrict__ x,         // [B, T, N4]
    const float4* __restrict__ thresh4,   // [N4]
    const float4* __restrict__ taux4,     // [N4]
    float4* __restrict__ spikes,          // [B, T, N4]
    float4* __restrict__ mems)            // [B, T, N4]
{
    const int idx = blockIdx.x * blockDim.x + threadIdx.x;  // [0, B*N4)
    const int n4 = idx & (N4 - 1);
    const int b  = idx >> 12;             // idx / N4

    const float4 th = thresh4[n4];
    const float4 tx = taux4[n4];

    float4 sig;
    sig.x = 1.0f / (1.0f + __expf(-tx.x));
    sig.y = 1.0f / (1.0f + __expf(-tx.y));
    sig.z = 1.0f / (1.0f + __expf(-tx.z));
    sig.w = 1.0f / (1.0f + __expf(-tx.w));

    float4 mem = make_float4(0.f, 0.f, 0.f, 0.f);

    const size_t base = (size_t)b * T * N4 + n4;
    const float4* xp = x + base;
    float4* sp = spikes + base;
    float4* mp = mems + base;

    // 4-deep prefetch pipeline: buf[i] holds x[t+i] while we compute t..t+3.
    float4 buf[4];
    #pragma unroll
    for (int i = 0; i < 4; ++i)
        buf[i] = __ldcs(&xp[(size_t)i * N4]);

    #pragma unroll
    for (int t = 0; t < T; t += 4) {
        #pragma unroll
        for (int i = 0; i < 4; ++i) {
            const float4 xv = buf[i];
            // Refill this pipeline slot 4 steps ahead (issues before the
            // dependent compute below retires -> 4 loads always in flight).
            if (t + 4 < T)
                buf[i] = __ldcs(&xp[(size_t)(t + 4 + i) * N4]);

            // leaky integration: mem += sig * (x - mem)
            float mx = fmaf(sig.x, xv.x - mem.x, mem.x);
            float my = fmaf(sig.y, xv.y - mem.y, mem.y);
            float mz = fmaf(sig.z, xv.z - mem.z, mem.z);
            float mw = fmaf(sig.w, xv.w - mem.w, mem.w);

            // Heaviside fire (>= threshold), hard reset
            float4 s;
            s.x = (mx >= th.x) ? 1.0f : 0.0f;
            s.y = (my >= th.y) ? 1.0f : 0.0f;
            s.z = (mz >= th.z) ? 1.0f : 0.0f;
            s.w = (mw >= th.w) ? 1.0f : 0.0f;

            mem.x = (s.x != 0.0f) ? 0.0f : mx;
            mem.y = (s.y != 0.0f) ? 0.0f : my;
            mem.z = (s.z != 0.0f) ? 0.0f : mz;
            mem.w = (s.w != 0.0f) ? 0.0f : mw;

            sp[(size_t)(t + i) * N4] = s;
            mp[(size_t)(t + i) * N4] = mem;
        }
    }
}

extern "C" void kernel_launch(void* const* d_in, const int* in_sizes, int n_in,
                              void* d_out, int out_size)
{
    const float4* x    = (const float4*)d_in[0];
    const float4* th   = (const float4*)d_in[1];
    const float4* taux = (const float4*)d_in[2];

    float4* spikes = (float4*)d_out;
    float4* mems   = (float4*)((float*)d_out + (size_t)B * T * N);

    const int total = B * N4;             // 131072 threads
    const int tpb = 128;                  // 1024 blocks -> 6.9/SM, small tail
    lif_kernel<<<total / tpb, tpb>>>(x, th, taux, spikes, mems);
}